// round 1
// baseline (speedup 1.0000x reference)
#include <cuda_runtime.h>

// Problem constants
#define N_INV   1152
#define N_OUTV  10
#define D_INV   8
#define D_OUTV  16
#define BATCHV  256
#define JO      160                 // N_OUT * D_OUT
#define UH_PER_B (N_INV * JO)       // 184320
#define IJ      (N_INV * N_OUTV)   // 11520

// Scratch (static device globals — no allocation at runtime)
__device__ float g_uhat[(size_t)BATCHV * UH_PER_B];   // ~180 MiB
__device__ float g_s[BATCHV * JO];
__device__ float g_v[BATCHV * JO];
__device__ float g_blog[IJ];
__device__ float g_a[IJ];
__device__ float g_c[IJ];

// ---------------------------------------------------------------------------
// Zero all routing state (must run every kernel_launch call: deterministic)
// ---------------------------------------------------------------------------
__global__ void k_zero() {
    int tid = blockIdx.x * blockDim.x + threadIdx.x;
    int nt  = gridDim.x * blockDim.x;
    for (int k = tid; k < BATCHV * JO; k += nt) g_s[k] = 0.f;
    for (int k = tid; k < IJ; k += nt) { g_blog[k] = 0.f; g_a[k] = 0.f; }
}

// ---------------------------------------------------------------------------
// u_hat[b,i,j,o] = sum_d W[i,j,o,d] * x[b,d,i]; also accumulate
// s1[b,j,o] += 0.1 * sum_i u_hat  (iter-1 coupling is exactly 1/10).
// Block: 8 i's x 64 b's; thread t in [0,160) owns (j,o)=(t/16, t%16).
// W chunk lives in registers (64 f32/thread) -> W read from DRAM exactly once.
// ---------------------------------------------------------------------------
__global__ __launch_bounds__(160) void k_uhat(const float* __restrict__ x,
                                              const float* __restrict__ w) {
    const int t  = threadIdx.x;            // 0..159
    const int i0 = blockIdx.x * 8;
    const int b0 = blockIdx.y * 64;
    __shared__ float xs[64];               // xs[d*8 + ii]

    float4 w0[8], w1[8];
    #pragma unroll
    for (int ii = 0; ii < 8; ii++) {
        const float4* wb =
            reinterpret_cast<const float4*>(w + ((size_t)(i0 + ii) * JO + t) * 8);
        w0[ii] = wb[0];
        w1[ii] = wb[1];
    }

    for (int b = b0; b < b0 + 64; b++) {
        if (t < 64)
            xs[t] = x[(size_t)b * (D_INV * N_INV) + (t >> 3) * N_INV + i0 + (t & 7)];
        __syncthreads();

        float sacc = 0.f;
        size_t base = (size_t)b * UH_PER_B + (size_t)i0 * JO + t;
        #pragma unroll
        for (int ii = 0; ii < 8; ii++) {
            float val = w0[ii].x * xs[ii]      + w0[ii].y * xs[8 + ii]
                      + w0[ii].z * xs[16 + ii] + w0[ii].w * xs[24 + ii]
                      + w1[ii].x * xs[32 + ii] + w1[ii].y * xs[40 + ii]
                      + w1[ii].z * xs[48 + ii] + w1[ii].w * xs[56 + ii];
            g_uhat[base + (size_t)ii * JO] = val;
            sacc += val;
        }
        atomicAdd(&g_s[b * JO + t], 0.1f * sacc);
        __syncthreads();
    }
}

// ---------------------------------------------------------------------------
// squash: v = (|s|^2/(1+|s|^2)) * s/sqrt(|s|^2 + eps), per (b,j) 16-vector.
// outp == nullptr -> write internal g_v, else write final output.
// ---------------------------------------------------------------------------
__global__ void k_squash(float* __restrict__ outp) {
    int idx = blockIdx.x * blockDim.x + threadIdx.x;   // (b*N_OUT + j)
    if (idx >= BATCHV * N_OUTV) return;
    const float4* sp = reinterpret_cast<const float4*>(g_s + idx * D_OUTV);
    float4 s0 = sp[0], s1 = sp[1], s2 = sp[2], s3 = sp[3];
    float sq = s0.x*s0.x + s0.y*s0.y + s0.z*s0.z + s0.w*s0.w
             + s1.x*s1.x + s1.y*s1.y + s1.z*s1.z + s1.w*s1.w
             + s2.x*s2.x + s2.y*s2.y + s2.z*s2.z + s2.w*s2.w
             + s3.x*s3.x + s3.y*s3.y + s3.z*s3.z + s3.w*s3.w;
    float fac = (sq / (1.f + sq)) * rsqrtf(sq + 1e-9f);
    float* dst = (outp ? outp : g_v) + idx * D_OUTV;
    float4* d4 = reinterpret_cast<float4*>(dst);
    s0.x*=fac; s0.y*=fac; s0.z*=fac; s0.w*=fac;
    s1.x*=fac; s1.y*=fac; s1.z*=fac; s1.w*=fac;
    s2.x*=fac; s2.y*=fac; s2.z*=fac; s2.w*=fac;
    s3.x*=fac; s3.y*=fac; s3.z*=fac; s3.w*=fac;
    d4[0] = s0; d4[1] = s1; d4[2] = s2; d4[3] = s3;
}

// ---------------------------------------------------------------------------
// agreement: a[i,j] += sum_b sum_o u_hat[b,i,j,o] * v[b,j,o]
// Block: 64 i's x 16 b's. Each (i,j) row = one float4x4 dot.
// partial[p] owned exclusively by thread (p mod 256) -> no smem races.
// ---------------------------------------------------------------------------
__global__ __launch_bounds__(256) void k_agree() {
    const int t  = threadIdx.x;            // 0..255
    const int i0 = blockIdx.x * 64;
    const int b0 = blockIdx.y * 16;
    __shared__ float partial[640];
    __shared__ float vsh[JO];

    for (int p = t; p < 640; p += 256) partial[p] = 0.f;

    for (int b = b0; b < b0 + 16; b++) {
        __syncthreads();
        if (t < JO) vsh[t] = g_v[b * JO + t];
        __syncthreads();
        size_t base = (size_t)b * UH_PER_B + (size_t)i0 * JO;
        for (int p = t; p < 640; p += 256) {
            int il = p / 10, j = p - il * 10;
            const float4* up =
                reinterpret_cast<const float4*>(g_uhat + base + (size_t)il * JO + j * 16);
            const float4* vp = reinterpret_cast<const float4*>(vsh + j * 16);
            float4 u0 = up[0], u1 = up[1], u2 = up[2], u3 = up[3];
            float4 v0 = vp[0], v1 = vp[1], v2 = vp[2], v3 = vp[3];
            float d = u0.x*v0.x + u0.y*v0.y + u0.z*v0.z + u0.w*v0.w
                    + u1.x*v1.x + u1.y*v1.y + u1.z*v1.z + u1.w*v1.w
                    + u2.x*v2.x + u2.y*v2.y + u2.z*v2.z + u2.w*v2.w
                    + u3.x*v3.x + u3.y*v3.y + u3.z*v3.z + u3.w*v3.w;
            partial[p] += d;
        }
    }
    __syncthreads();
    for (int p = t; p < 640; p += 256) {
        int il = p / 10, j = p - il * 10;
        atomicAdd(&g_a[(i0 + il) * N_OUTV + j], partial[p]);
    }
}

// ---------------------------------------------------------------------------
// update: b += a/256; c = softmax_j(b); zero a; zero s (for next s-pass).
// 1280 threads total.
// ---------------------------------------------------------------------------
__global__ void k_update() {
    int gid = blockIdx.x * blockDim.x + threadIdx.x;
    if (gid < N_INV) {
        float bl[10], ex[10];
        float mx = -1e30f;
        #pragma unroll
        for (int j = 0; j < 10; j++) {
            float nb = g_blog[gid * 10 + j] + g_a[gid * 10 + j] * (1.0f / BATCHV);
            g_blog[gid * 10 + j] = nb;
            g_a[gid * 10 + j] = 0.f;
            bl[j] = nb;
            mx = fmaxf(mx, nb);
        }
        float sum = 0.f;
        #pragma unroll
        for (int j = 0; j < 10; j++) { ex[j] = expf(bl[j] - mx); sum += ex[j]; }
        float inv = 1.f / sum;
        #pragma unroll
        for (int j = 0; j < 10; j++) g_c[gid * 10 + j] = ex[j] * inv;
    }
    int nt = gridDim.x * blockDim.x;
    for (int k = gid; k < BATCHV * JO; k += nt) g_s[k] = 0.f;
}

// ---------------------------------------------------------------------------
// s-pass: s[b,j,o] = sum_i c[i,j] * u_hat[b,i,j,o]. One block per b,
// 640 threads: thread = (jo, i mod 4). Fully coalesced 2560B/step reads.
// ---------------------------------------------------------------------------
__global__ __launch_bounds__(640) void k_spass() {
    const int t = threadIdx.x;   // 0..639
    const int b = blockIdx.x;
    __shared__ float csh[IJ];    // 46 KB
    __shared__ float red[640];

    for (int k = t; k < IJ; k += 640) csh[k] = g_c[k];
    __syncthreads();

    const int jo = t % JO;
    const int i4 = t / JO;       // 0..3
    const int j  = jo >> 4;
    const float* up = g_uhat + (size_t)b * UH_PER_B + jo;

    float a0 = 0.f, a1 = 0.f, a2 = 0.f, a3 = 0.f;
    for (int i = i4; i < N_INV; i += 16) {
        a0 = fmaf(csh[(i     ) * 10 + j], up[(size_t)(i     ) * JO], a0);
        a1 = fmaf(csh[(i +  4) * 10 + j], up[(size_t)(i +  4) * JO], a1);
        a2 = fmaf(csh[(i +  8) * 10 + j], up[(size_t)(i +  8) * JO], a2);
        a3 = fmaf(csh[(i + 12) * 10 + j], up[(size_t)(i + 12) * JO], a3);
    }
    red[t] = (a0 + a1) + (a2 + a3);
    __syncthreads();
    if (t < JO)
        g_s[b * JO + t] = red[t] + red[t + JO] + red[t + 2 * JO] + red[t + 3 * JO];
}

// ---------------------------------------------------------------------------
extern "C" void kernel_launch(void* const* d_in, const int* in_sizes, int n_in,
                              void* d_out, int out_size) {
    const float* x = (const float*)d_in[0];
    const float* w = (const float*)d_in[1];
    // Defensive: identify by element counts in case metadata order differs.
    if (n_in >= 2 && in_sizes[0] == N_INV * N_OUTV * D_OUTV * D_INV
                  && in_sizes[1] == BATCHV * D_INV * N_INV) {
        const float* tmp = x; x = w; w = tmp;
    }
    float* out = (float*)d_out;

    k_zero<<<64, 256>>>();
    k_uhat<<<dim3(144, 4), 160>>>(x, w);          // write u_hat + s1 (c = 0.1)
    // ---- iteration 1 tail ----
    k_squash<<<10, 256>>>(nullptr);               // v1
    k_agree<<<dim3(18, 16), 256>>>();             // a1
    k_update<<<5, 256>>>();                       // b+=a1/256 -> c2; zero a,s
    // ---- iteration 2 ----
    k_spass<<<256, 640>>>();                      // s2
    k_squash<<<10, 256>>>(nullptr);               // v2
    k_agree<<<dim3(18, 16), 256>>>();             // a2
    k_update<<<5, 256>>>();                       // b+=a2/256 -> c3; zero a,s
    // ---- iteration 3 (agreement not needed) ----
    k_spass<<<256, 640>>>();                      // s3
    k_squash<<<10, 256>>>(out);                   // v3 -> output
}

// round 3
// speedup vs baseline: 1.1682x; 1.1682x over previous
#include <cuda_runtime.h>
#include <cuda_fp16.h>
#include <cstdint>
#include <cstddef>

// problem constants
#define NIN   1152
#define NOUT  10
#define DIN   8
#define DOUT  16
#define BB    256
#define JO    160
#define KD    9216
#define IJ    11520
#define KSPLIT 32
#define KCHUNK 288

// scratch (static device globals, no runtime allocation)
__device__ __half g_xh[(size_t)BB * KD];
__device__ __half g_xt[(size_t)KD * BB];
__device__ __half g_wt[(size_t)KD * JO];
__device__ __half g_mh[(size_t)KD * JO];
__device__ __half g_vh[BB * JO];
__device__ float  g_part[(size_t)KSPLIT * BB * JO];
__device__ float  g_c[IJ];
__device__ float  g_blog[IJ];

__device__ __forceinline__ unsigned int smem_u32(const void* p) {
    return (unsigned int)__cvta_generic_to_shared(p);
}

__device__ __forceinline__ void ldsm_x4(unsigned int& r0, unsigned int& r1,
                                        unsigned int& r2, unsigned int& r3,
                                        unsigned int addr) {
    asm volatile("ldmatrix.sync.aligned.m8n8.x4.shared.b16 {%0,%1,%2,%3}, [%4];"
                 : "=r"(r0), "=r"(r1), "=r"(r2), "=r"(r3) : "r"(addr));
}

__device__ __forceinline__ void ldsm_x2t(unsigned int& r0, unsigned int& r1,
                                         unsigned int addr) {
    asm volatile("ldmatrix.sync.aligned.m8n8.x2.trans.shared.b16 {%0,%1}, [%2];"
                 : "=r"(r0), "=r"(r1) : "r"(addr));
}

__device__ __forceinline__ void mma16816(float* c,
                                         unsigned int a0, unsigned int a1,
                                         unsigned int a2, unsigned int a3,
                                         unsigned int b0, unsigned int b1) {
    asm volatile(
        "mma.sync.aligned.m16n8k16.row.col.f32.f16.f16.f32 "
        "{%0,%1,%2,%3}, {%4,%5,%6,%7}, {%8,%9}, {%0,%1,%2,%3};"
        : "+f"(c[0]), "+f"(c[1]), "+f"(c[2]), "+f"(c[3])
        : "r"(a0), "r"(a1), "r"(a2), "r"(a3), "r"(b0), "r"(b1));
}

// prep_x: xh = fp16(x) same layout; xt = fp16(x) transposed, via 32x32 tiles.
__global__ __launch_bounds__(256) void k_prep_x(const float* __restrict__ x) {
    __shared__ float tile[32][33];
    const int di0 = blockIdx.x * 32;
    const int b0  = blockIdx.y * 32;
    const int tx = threadIdx.x & 31;
    const int ty = threadIdx.x >> 5;
    for (int q = 0; q < 4; q++) {
        int r = ty + q * 8;
        float v = x[(size_t)(b0 + r) * KD + di0 + tx];
        tile[r][tx] = v;
        g_xh[(size_t)(b0 + r) * KD + di0 + tx] = __float2half(v);
    }
    __syncthreads();
    for (int q = 0; q < 4; q++) {
        int r = ty + q * 8;
        g_xt[(size_t)(di0 + r) * BB + b0 + tx] = __float2half(tile[tx][r]);
    }
}

// prep_w: Wt[(d*NIN+i)][jo] = fp16(W[i][j][o][d]); init c = 0.1, blog = 0.
__global__ __launch_bounds__(160) void k_prep_w(const float* __restrict__ w) {
    __shared__ float sh[1280];
    const int i = blockIdx.x;
    const int t = threadIdx.x;
    for (int q = 0; q < 8; q++) {
        sh[t + q * 160] = w[(size_t)i * 1280 + t + q * 160];
    }
    __syncthreads();
    for (int d = 0; d < 8; d++) {
        g_wt[(size_t)(d * NIN + i) * JO + t] =
            __float2half(sh[(t >> 4) * 128 + (t & 15) * 8 + d]);
    }
    if (t < 10) {
        g_c[i * 10 + t] = 0.1f;
        g_blog[i * 10 + t] = 0.f;
    }
}

// GEMM s: part[split][b][jo] = sum_k xh[b][k] * (c[i(k),j(jo)] * Wt[k][jo]).
// 128 threads (4 warps), tile 16 b x 160 jo, 18 k-steps of 16.
// c-scaling fused into the B smem stage.
__global__ __launch_bounds__(128) void k_gemm_s() {
    __shared__ __align__(16) __half As[16 * 24];
    __shared__ __align__(16) __half Bs[16 * 168];
    const int t = threadIdx.x;
    const int lane = t & 31;
    const int w = t >> 5;
    const int split = blockIdx.x;
    const int m0 = blockIdx.y * 16;
    const int kbase = split * KCHUNK;

    float acc[5][4];
    for (int n = 0; n < 5; n++) {
        for (int q = 0; q < 4; q++) acc[n][q] = 0.f;
    }

    const unsigned int aaddr =
        smem_u32(As) + (unsigned int)(((lane & 15) * 24 + (lane >> 4) * 8) * 2);
    const unsigned int baddr =
        smem_u32(Bs) + (unsigned int)(((lane & 15) * 168) * 2);

    for (int kk = 0; kk < 18; kk++) {
        const int k0 = kbase + kk * 16;
        {
            int r = t >> 3;
            int c = (t & 7) * 2;
            *(uint32_t*)(As + r * 24 + c) =
                *(const uint32_t*)(g_xh + (size_t)(m0 + r) * KD + k0 + c);
        }
        for (int q = 0; q < 5; q++) {
            int e = t + q * 128;
            int r = e / 40;
            int c8 = e - r * 40;
            int di = k0 + r;
            int i = di - (di / NIN) * NIN;
            int j = c8 >> 2;
            float cw = g_c[i * 10 + j];
            uint2 raw = *(const uint2*)(g_wt + (size_t)di * JO + c8 * 4);
            __half2 h0 = *(__half2*)&raw.x;
            __half2 h1 = *(__half2*)&raw.y;
            float2 f0 = __half22float2(h0);
            float2 f1 = __half22float2(h1);
            uint2 outp;
            __half2 o0 = __floats2half2_rn(cw * f0.x, cw * f0.y);
            __half2 o1 = __floats2half2_rn(cw * f1.x, cw * f1.y);
            outp.x = *(unsigned int*)&o0;
            outp.y = *(unsigned int*)&o1;
            *(uint2*)(Bs + r * 168 + c8 * 4) = outp;
        }
        __syncthreads();
        unsigned int a0, a1, a2, a3;
        ldsm_x4(a0, a1, a2, a3, aaddr);
        for (int nt = 0; nt < 5; nt++) {
            unsigned int b0, b1;
            ldsm_x2t(b0, b1, baddr + (unsigned int)((w * 40 + nt * 8) * 2));
            mma16816(acc[nt], a0, a1, a2, a3, b0, b1);
        }
        __syncthreads();
    }
    const int g = lane >> 2;
    const int c2 = (lane & 3) * 2;
    float* base = g_part + ((size_t)split * BB + m0) * JO;
    for (int nt = 0; nt < 5; nt++) {
        int col = w * 40 + nt * 8 + c2;
        *(float2*)(base + g * JO + col) = make_float2(acc[nt][0], acc[nt][1]);
        *(float2*)(base + (g + 8) * JO + col) = make_float2(acc[nt][2], acc[nt][3]);
    }
}

// squash: s = sum over splits of part; v = squash(s); store fp16 v (+ fp32 out).
__global__ __launch_bounds__(160) void k_squash(float* __restrict__ outp) {
    __shared__ float sh[JO];
    const int b = blockIdx.x;
    const int t = threadIdx.x;
    float s = 0.f;
    for (int sp = 0; sp < KSPLIT; sp++) {
        s += g_part[((size_t)sp * BB + b) * JO + t];
    }
    sh[t] = s * s;
    __syncthreads();
    const int j = t >> 4;
    float sq = 0.f;
    for (int o = 0; o < 16; o++) sq += sh[j * 16 + o];
    float fac = (sq / (1.f + sq)) * rsqrtf(sq + 1e-9f);
    float v = s * fac;
    g_vh[b * JO + t] = __float2half(v);
    if (outp) outp[b * JO + t] = v;
}

// GEMM M: Mh[di][jo] = sum_b xt[di][b] * vh[b][jo]; K = 256.
// 128 threads (4 warps), tile 64 di x 160 jo; warp w owns rows w*16..w*16+15.
__global__ __launch_bounds__(128) void k_gemm_m() {
    __shared__ __align__(16) __half As[64 * 24];
    __shared__ __align__(16) __half Bs[16 * 168];
    const int t = threadIdx.x;
    const int lane = t & 31;
    const int w = t >> 5;
    const int m0 = blockIdx.x * 64;

    float acc[20][4];
    for (int n = 0; n < 20; n++) {
        for (int q = 0; q < 4; q++) acc[n][q] = 0.f;
    }

    const unsigned int aaddr = smem_u32(As) +
        (unsigned int)(((w * 16 + (lane & 15)) * 24 + (lane >> 4) * 8) * 2);
    const unsigned int baddr = smem_u32(Bs) +
        (unsigned int)(((lane & 15) * 168) * 2);

    for (int kk = 0; kk < 16; kk++) {
        const int k0 = kk * 16;
        for (int q = 0; q < 4; q++) {
            int e = t + q * 128;
            int r = e >> 3;
            int c = (e & 7) * 2;
            *(uint32_t*)(As + r * 24 + c) =
                *(const uint32_t*)(g_xt + (size_t)(m0 + r) * BB + k0 + c);
        }
        for (int q = 0; q < 5; q++) {
            int e = t + q * 128;
            int r = e / 40;
            int c8 = e - r * 40;
            *(uint2*)(Bs + r * 168 + c8 * 4) =
                *(const uint2*)(g_vh + (size_t)(k0 + r) * JO + c8 * 4);
        }
        __syncthreads();
        unsigned int a0, a1, a2, a3;
        ldsm_x4(a0, a1, a2, a3, aaddr);
        for (int nt = 0; nt < 20; nt++) {
            unsigned int b0, b1;
            ldsm_x2t(b0, b1, baddr + (unsigned int)((nt * 8) * 2));
            mma16816(acc[nt], a0, a1, a2, a3, b0, b1);
        }
        __syncthreads();
    }
    const int g = lane >> 2;
    const int c2 = (lane & 3) * 2;
    const int row = m0 + w * 16 + g;
    for (int nt = 0; nt < 20; nt++) {
        int col = nt * 8 + c2;
        __half2 lo = __floats2half2_rn(acc[nt][0], acc[nt][1]);
        __half2 hi = __floats2half2_rn(acc[nt][2], acc[nt][3]);
        *(__half2*)(g_mh + (size_t)row * JO + col) = lo;
        *(__half2*)(g_mh + (size_t)(row + 8) * JO + col) = hi;
    }
}

// route: a[i][j] = sum_{d,o} Wt*Mh; blog += a/256; c = softmax_j(blog).
__global__ __launch_bounds__(128) void k_route() {
    const int i = blockIdx.x * 128 + threadIdx.x;
    if (i >= NIN) return;
    float a[10];
    for (int j = 0; j < 10; j++) a[j] = 0.f;
    for (int d = 0; d < 8; d++) {
        const __half2* mrow = (const __half2*)g_mh + (size_t)(d * NIN + i) * 80;
        const __half2* wrow = (const __half2*)g_wt + (size_t)(d * NIN + i) * 80;
        for (int j = 0; j < 10; j++) {
            float accj = 0.f;
            for (int q = 0; q < 8; q++) {
                float2 m = __half22float2(mrow[j * 8 + q]);
                float2 wv = __half22float2(wrow[j * 8 + q]);
                accj += m.x * wv.x + m.y * wv.y;
            }
            a[j] += accj;
        }
    }
    float bl[10];
    float ex[10];
    float mx = -1e30f;
    for (int j = 0; j < 10; j++) {
        float nb = g_blog[i * 10 + j] + a[j] * (1.0f / 256.0f);
        g_blog[i * 10 + j] = nb;
        bl[j] = nb;
        mx = fmaxf(mx, nb);
    }
    float sum = 0.f;
    for (int j = 0; j < 10; j++) {
        ex[j] = expf(bl[j] - mx);
        sum += ex[j];
    }
    float inv = 1.f / sum;
    for (int j = 0; j < 10; j++) {
        g_c[i * 10 + j] = ex[j] * inv;
    }
}

extern "C" void kernel_launch(void* const* d_in, const int* in_sizes, int n_in,
                              void* d_out, int out_size) {
    const float* x = (const float*)d_in[0];
    const float* w = (const float*)d_in[1];
    if (n_in >= 2 && in_sizes[0] == NIN * NOUT * DOUT * DIN
                  && in_sizes[1] == BB * DIN * NIN) {
        const float* tmp = x;
        x = w;
        w = tmp;
    }
    float* out = (float*)d_out;

    k_prep_x<<<dim3(KD / 32, BB / 32), 256>>>(x);
    k_prep_w<<<NIN, 160>>>(w);

    k_gemm_s<<<dim3(KSPLIT, BB / 16), 128>>>();
    k_squash<<<BB, 160>>>((float*)0);
    k_gemm_m<<<KD / 64, 128>>>();
    k_route<<<(NIN + 127) / 128, 128>>>();

    k_gemm_s<<<dim3(KSPLIT, BB / 16), 128>>>();
    k_squash<<<BB, 160>>>((float*)0);
    k_gemm_m<<<KD / 64, 128>>>();
    k_route<<<(NIN + 127) / 128, 128>>>();

    k_gemm_s<<<dim3(KSPLIT, BB / 16), 128>>>();
    k_squash<<<BB, 160>>>(out);
}

// round 4
// speedup vs baseline: 1.8001x; 1.5408x over previous
#include <cuda_runtime.h>
#include <cuda_fp16.h>
#include <cstdint>
#include <cstddef>

// problem constants
#define NIN   1152
#define NOUT  10
#define DIN   8
#define DOUT  16
#define BB    256
#define JO    160
#define KD    9216
#define IJ    11520
#define KSPLIT 32
#define KCHUNK 288

// scratch (static device globals, no runtime allocation)
__device__ __half g_xh[(size_t)BB * KD];
__device__ __half g_xt[(size_t)KD * BB];
__device__ __half g_wt[(size_t)KD * JO];
__device__ __half g_mh[(size_t)KD * JO];
__device__ __half g_vh[BB * JO];
__device__ float  g_part[(size_t)KSPLIT * BB * JO];
__device__ float  g_c[IJ];
__device__ float  g_blog[IJ];

__device__ __forceinline__ unsigned int smem_u32(const void* p) {
    return (unsigned int)__cvta_generic_to_shared(p);
}

__device__ __forceinline__ void ldsm_x4(unsigned int& r0, unsigned int& r1,
                                        unsigned int& r2, unsigned int& r3,
                                        unsigned int addr) {
    asm volatile("ldmatrix.sync.aligned.m8n8.x4.shared.b16 {%0,%1,%2,%3}, [%4];"
                 : "=r"(r0), "=r"(r1), "=r"(r2), "=r"(r3) : "r"(addr));
}

__device__ __forceinline__ void ldsm_x2t(unsigned int& r0, unsigned int& r1,
                                         unsigned int addr) {
    asm volatile("ldmatrix.sync.aligned.m8n8.x2.trans.shared.b16 {%0,%1}, [%2];"
                 : "=r"(r0), "=r"(r1) : "r"(addr));
}

__device__ __forceinline__ void mma16816(float* c,
                                         unsigned int a0, unsigned int a1,
                                         unsigned int a2, unsigned int a3,
                                         unsigned int b0, unsigned int b1) {
    asm volatile(
        "mma.sync.aligned.m16n8k16.row.col.f32.f16.f16.f32 "
        "{%0,%1,%2,%3}, {%4,%5,%6,%7}, {%8,%9}, {%0,%1,%2,%3};"
        : "+f"(c[0]), "+f"(c[1]), "+f"(c[2]), "+f"(c[3])
        : "r"(a0), "r"(a1), "r"(a2), "r"(a3), "r"(b0), "r"(b1));
}

// prep_x: xh = fp16(x) same layout; xt = fp16(x) transposed, via 32x32 tiles.
__global__ __launch_bounds__(256) void k_prep_x(const float* __restrict__ x) {
    __shared__ float tile[32][33];
    const int di0 = blockIdx.x * 32;
    const int b0  = blockIdx.y * 32;
    const int tx = threadIdx.x & 31;
    const int ty = threadIdx.x >> 5;
    #pragma unroll
    for (int q = 0; q < 4; q++) {
        int r = ty + q * 8;
        float v = x[(size_t)(b0 + r) * KD + di0 + tx];
        tile[r][tx] = v;
        g_xh[(size_t)(b0 + r) * KD + di0 + tx] = __float2half(v);
    }
    __syncthreads();
    #pragma unroll
    for (int q = 0; q < 4; q++) {
        int r = ty + q * 8;
        g_xt[(size_t)(di0 + r) * BB + b0 + tx] = __float2half(tile[tx][r]);
    }
}

// prep_w: Wt[(d*NIN+i)][jo] = fp16(W[i][j][o][d]); init c = 0.1, blog = 0.
__global__ __launch_bounds__(160) void k_prep_w(const float* __restrict__ w) {
    __shared__ float sh[1280];
    const int i = blockIdx.x;
    const int t = threadIdx.x;
    #pragma unroll
    for (int q = 0; q < 8; q++) {
        sh[t + q * 160] = w[(size_t)i * 1280 + t + q * 160];
    }
    __syncthreads();
    #pragma unroll
    for (int d = 0; d < 8; d++) {
        g_wt[(size_t)(d * NIN + i) * JO + t] =
            __float2half(sh[(t >> 4) * 128 + (t & 15) * 8 + d]);
    }
    if (t < 10) {
        g_c[i * 10 + t] = 0.1f;
        g_blog[i * 10 + t] = 0.f;
    }
}

// GEMM s: part[split][b][jo] = sum_k xh[b][k] * (c[i(k),j(jo)] * Wt[k][jo]).
// 128 threads (4 warps), tile 16 b x 160 jo, 18 k-steps of 16.
// c-scaling fused into the B smem stage.
__global__ __launch_bounds__(128) void k_gemm_s() {
    __shared__ __align__(16) __half As[16 * 24];
    __shared__ __align__(16) __half Bs[16 * 168];
    const int t = threadIdx.x;
    const int lane = t & 31;
    const int w = t >> 5;
    const int split = blockIdx.x;
    const int m0 = blockIdx.y * 16;
    const int kbase = split * KCHUNK;

    float acc[5][4];
    #pragma unroll
    for (int n = 0; n < 5; n++) {
        #pragma unroll
        for (int q = 0; q < 4; q++) acc[n][q] = 0.f;
    }

    const unsigned int aaddr =
        smem_u32(As) + (unsigned int)(((lane & 15) * 24 + (lane >> 4) * 8) * 2);
    const unsigned int baddr =
        smem_u32(Bs) + (unsigned int)(((lane & 15) * 168) * 2);

    for (int kk = 0; kk < 18; kk++) {
        const int k0 = kbase + kk * 16;
        {
            int r = t >> 3;
            int c = (t & 7) * 2;
            *(uint32_t*)(As + r * 24 + c) =
                *(const uint32_t*)(g_xh + (size_t)(m0 + r) * KD + k0 + c);
        }
        #pragma unroll
        for (int q = 0; q < 5; q++) {
            int e = t + q * 128;
            int r = e / 40;
            int c8 = e - r * 40;
            int di = k0 + r;
            int i = di - (di / NIN) * NIN;
            int j = c8 >> 2;
            float cw = g_c[i * 10 + j];
            uint2 raw = *(const uint2*)(g_wt + (size_t)di * JO + c8 * 4);
            __half2 h0 = *(__half2*)&raw.x;
            __half2 h1 = *(__half2*)&raw.y;
            float2 f0 = __half22float2(h0);
            float2 f1 = __half22float2(h1);
            uint2 outp;
            __half2 o0 = __floats2half2_rn(cw * f0.x, cw * f0.y);
            __half2 o1 = __floats2half2_rn(cw * f1.x, cw * f1.y);
            outp.x = *(unsigned int*)&o0;
            outp.y = *(unsigned int*)&o1;
            *(uint2*)(Bs + r * 168 + c8 * 4) = outp;
        }
        __syncthreads();
        unsigned int a0, a1, a2, a3;
        ldsm_x4(a0, a1, a2, a3, aaddr);
        #pragma unroll
        for (int nt = 0; nt < 5; nt++) {
            unsigned int b0, b1;
            ldsm_x2t(b0, b1, baddr + (unsigned int)((w * 40 + nt * 8) * 2));
            mma16816(acc[nt], a0, a1, a2, a3, b0, b1);
        }
        __syncthreads();
    }
    const int g = lane >> 2;
    const int c2 = (lane & 3) * 2;
    float* base = g_part + ((size_t)split * BB + m0) * JO;
    #pragma unroll
    for (int nt = 0; nt < 5; nt++) {
        int col = w * 40 + nt * 8 + c2;
        *(float2*)(base + g * JO + col) = make_float2(acc[nt][0], acc[nt][1]);
        *(float2*)(base + (g + 8) * JO + col) = make_float2(acc[nt][2], acc[nt][3]);
    }
}

// squash: s = sum over splits of part (4-way split across threads);
// v = squash(s); store fp16 v (+ fp32 out on last iteration).
__global__ __launch_bounds__(640) void k_squash(float* __restrict__ outp) {
    __shared__ float red[640];
    __shared__ float sh[JO];
    const int b = blockIdx.x;
    const int t = threadIdx.x;
    const int jo = t % JO;
    const int qq = t / JO;          // 0..3, covers 8 splits each
    float s = 0.f;
    #pragma unroll
    for (int sp = 0; sp < 8; sp++) {
        s += g_part[((size_t)(qq * 8 + sp) * BB + b) * JO + jo];
    }
    red[t] = s;
    __syncthreads();
    if (t < JO) {
        float sv = red[t] + red[t + JO] + red[t + 2 * JO] + red[t + 3 * JO];
        red[t] = sv;
        sh[t] = sv * sv;
    }
    __syncthreads();
    if (t < JO) {
        const int j = t >> 4;
        float sq = 0.f;
        #pragma unroll
        for (int o = 0; o < 16; o++) sq += sh[j * 16 + o];
        float fac = (sq / (1.f + sq)) * rsqrtf(sq + 1e-9f);
        float v = red[t] * fac;
        g_vh[b * JO + t] = __float2half(v);
        if (outp) outp[b * JO + t] = v;
    }
}

// GEMM M: Mh[di][jo] = sum_b xt[di][b] * vh[b][jo]; K = 256.
// 128 threads (4 warps), tile 64 di x 160 jo; warp w owns rows w*16..w*16+15.
__global__ __launch_bounds__(128) void k_gemm_m() {
    __shared__ __align__(16) __half As[64 * 24];
    __shared__ __align__(16) __half Bs[16 * 168];
    const int t = threadIdx.x;
    const int lane = t & 31;
    const int w = t >> 5;
    const int m0 = blockIdx.x * 64;

    float acc[20][4];
    #pragma unroll
    for (int n = 0; n < 20; n++) {
        #pragma unroll
        for (int q = 0; q < 4; q++) acc[n][q] = 0.f;
    }

    const unsigned int aaddr = smem_u32(As) +
        (unsigned int)(((w * 16 + (lane & 15)) * 24 + (lane >> 4) * 8) * 2);
    const unsigned int baddr = smem_u32(Bs) +
        (unsigned int)(((lane & 15) * 168) * 2);

    for (int kk = 0; kk < 16; kk++) {
        const int k0 = kk * 16;
        #pragma unroll
        for (int q = 0; q < 4; q++) {
            int e = t + q * 128;
            int r = e >> 3;
            int c = (e & 7) * 2;
            *(uint32_t*)(As + r * 24 + c) =
                *(const uint32_t*)(g_xt + (size_t)(m0 + r) * BB + k0 + c);
        }
        #pragma unroll
        for (int q = 0; q < 5; q++) {
            int e = t + q * 128;
            int r = e / 40;
            int c8 = e - r * 40;
            *(uint2*)(Bs + r * 168 + c8 * 4) =
                *(const uint2*)(g_vh + (size_t)(k0 + r) * JO + c8 * 4);
        }
        __syncthreads();
        unsigned int a0, a1, a2, a3;
        ldsm_x4(a0, a1, a2, a3, aaddr);
        #pragma unroll
        for (int nt = 0; nt < 20; nt++) {
            unsigned int b0, b1;
            ldsm_x2t(b0, b1, baddr + (unsigned int)((nt * 8) * 2));
            mma16816(acc[nt], a0, a1, a2, a3, b0, b1);
        }
        __syncthreads();
    }
    const int g = lane >> 2;
    const int c2 = (lane & 3) * 2;
    const int row = m0 + w * 16 + g;
    #pragma unroll
    for (int nt = 0; nt < 20; nt++) {
        int col = nt * 8 + c2;
        __half2 lo = __floats2half2_rn(acc[nt][0], acc[nt][1]);
        __half2 hi = __floats2half2_rn(acc[nt][2], acc[nt][3]);
        *(__half2*)(g_mh + (size_t)row * JO + col) = lo;
        *(__half2*)(g_mh + (size_t)(row + 8) * JO + col) = hi;
    }
}

// route: a[i][j] = sum_{d,o} Wt*Mh; blog += a/256; c = softmax_j(blog).
// Block: 96 i's x 10 j's = 960 threads; thread computes one (i,j) dot.
__global__ __launch_bounds__(960) void k_route() {
    __shared__ float sa[960];
    const int t = threadIdx.x;
    const int il = t / 10;
    const int j  = t - il * 10;
    const int i  = blockIdx.x * 96 + il;

    float a = 0.f;
    #pragma unroll
    for (int d = 0; d < 8; d++) {
        const __half2* mrow = (const __half2*)g_mh + (size_t)(d * NIN + i) * 80 + j * 8;
        const __half2* wrow = (const __half2*)g_wt + (size_t)(d * NIN + i) * 80 + j * 8;
        #pragma unroll
        for (int q = 0; q < 8; q++) {
            float2 m = __half22float2(mrow[q]);
            float2 wv = __half22float2(wrow[q]);
            a += m.x * wv.x + m.y * wv.y;
        }
    }
    sa[t] = a;
    __syncthreads();

    if (t < 96) {
        const int ii = blockIdx.x * 96 + t;
        float bl[10];
        float ex[10];
        float mx = -1e30f;
        #pragma unroll
        for (int j2 = 0; j2 < 10; j2++) {
            float nb = g_blog[ii * 10 + j2] + sa[t * 10 + j2] * (1.0f / 256.0f);
            g_blog[ii * 10 + j2] = nb;
            bl[j2] = nb;
            mx = fmaxf(mx, nb);
        }
        float sum = 0.f;
        #pragma unroll
        for (int j2 = 0; j2 < 10; j2++) {
            ex[j2] = expf(bl[j2] - mx);
            sum += ex[j2];
        }
        float inv = 1.f / sum;
        #pragma unroll
        for (int j2 = 0; j2 < 10; j2++) {
            g_c[ii * 10 + j2] = ex[j2] * inv;
        }
    }
}

extern "C" void kernel_launch(void* const* d_in, const int* in_sizes, int n_in,
                              void* d_out, int out_size) {
    const float* x = (const float*)d_in[0];
    const float* w = (const float*)d_in[1];
    if (n_in >= 2 && in_sizes[0] == NIN * NOUT * DOUT * DIN
                  && in_sizes[1] == BB * DIN * NIN) {
        const float* tmp = x;
        x = w;
        w = tmp;
    }
    float* out = (float*)d_out;

    k_prep_x<<<dim3(KD / 32, BB / 32), 256>>>(x);
    k_prep_w<<<NIN, 160>>>(w);

    k_gemm_s<<<dim3(KSPLIT, BB / 16), 128>>>();
    k_squash<<<BB, 640>>>((float*)0);
    k_gemm_m<<<KD / 64, 128>>>();
    k_route<<<NIN / 96, 960>>>();

    k_gemm_s<<<dim3(KSPLIT, BB / 16), 128>>>();
    k_squash<<<BB, 640>>>((float*)0);
    k_gemm_m<<<KD / 64, 128>>>();
    k_route<<<NIN / 96, 960>>>();

    k_gemm_s<<<dim3(KSPLIT, BB / 16), 128>>>();
    k_squash<<<BB, 640>>>(out);
}

// round 5
// speedup vs baseline: 2.7234x; 1.5129x over previous
#include <cuda_runtime.h>
#include <cuda_fp16.h>
#include <cstdint>
#include <cstddef>

// problem constants
#define NIN   1152
#define NOUT  10
#define DIN   8
#define DOUT  16
#define BB    256
#define JO    160
#define KD    9216
#define IJ    11520
#define KSPLIT 32
#define KCHUNK 288

// Row index convention for the contraction dim: r = i*8 + d  (capsule-major).
// scratch (static device globals, no runtime allocation)
__device__ __half g_xh[(size_t)BB * KD];      // [b][r]
__device__ __half g_xt[(size_t)KD * BB];      // [r][b]
__device__ __half g_wt[(size_t)KD * JO];      // [r][jo]
__device__ __half g_vh[BB * JO];              // [b][jo]
__device__ float  g_part[(size_t)KSPLIT * BB * JO];
__device__ float  g_c[IJ];
__device__ float  g_blog[IJ];

__device__ __forceinline__ unsigned int smem_u32(const void* p) {
    return (unsigned int)__cvta_generic_to_shared(p);
}

__device__ __forceinline__ void ldsm_x4(unsigned int& r0, unsigned int& r1,
                                        unsigned int& r2, unsigned int& r3,
                                        unsigned int addr) {
    asm volatile("ldmatrix.sync.aligned.m8n8.x4.shared.b16 {%0,%1,%2,%3}, [%4];"
                 : "=r"(r0), "=r"(r1), "=r"(r2), "=r"(r3) : "r"(addr));
}

__device__ __forceinline__ void ldsm_x2t(unsigned int& r0, unsigned int& r1,
                                         unsigned int addr) {
    asm volatile("ldmatrix.sync.aligned.m8n8.x2.trans.shared.b16 {%0,%1}, [%2];"
                 : "=r"(r0), "=r"(r1) : "r"(addr));
}

__device__ __forceinline__ void mma16816(float* c,
                                         unsigned int a0, unsigned int a1,
                                         unsigned int a2, unsigned int a3,
                                         unsigned int b0, unsigned int b1) {
    asm volatile(
        "mma.sync.aligned.m16n8k16.row.col.f32.f16.f16.f32 "
        "{%0,%1,%2,%3}, {%4,%5,%6,%7}, {%8,%9}, {%0,%1,%2,%3};"
        : "+f"(c[0]), "+f"(c[1]), "+f"(c[2]), "+f"(c[3])
        : "r"(a0), "r"(a1), "r"(a2), "r"(a3), "r"(b0), "r"(b1));
}

// prep_x: xh[b][i*8+d] = fp16(x[b][d*NIN+i]); xt transposed likewise.
// 32x32 tiles; each tile lies within a single d (NIN divisible by 32).
__global__ __launch_bounds__(256) void k_prep_x(const float* __restrict__ x) {
    __shared__ float tile[32][33];
    const int di0 = blockIdx.x * 32;
    const int b0  = blockIdx.y * 32;
    const int d     = di0 / NIN;
    const int ibase = di0 - d * NIN;
    const int tx = threadIdx.x & 31;
    const int ty = threadIdx.x >> 5;
    #pragma unroll
    for (int q = 0; q < 4; q++) {
        int r = ty + q * 8;
        float v = x[(size_t)(b0 + r) * KD + di0 + tx];
        tile[r][tx] = v;
        g_xh[(size_t)(b0 + r) * KD + (ibase + tx) * 8 + d] = __float2half(v);
    }
    __syncthreads();
    #pragma unroll
    for (int q = 0; q < 4; q++) {
        int r = ty + q * 8;
        g_xt[(size_t)((ibase + r) * 8 + d) * BB + b0 + tx] = __float2half(tile[tx][r]);
    }
}

// prep_w: Wt[(i*8+d)][jo] = fp16(W[i][j][o][d]); init c = 0.1, blog = 0.
__global__ __launch_bounds__(160) void k_prep_w(const float* __restrict__ w) {
    __shared__ float sh[1280];
    const int i = blockIdx.x;
    const int t = threadIdx.x;
    #pragma unroll
    for (int q = 0; q < 8; q++) {
        sh[t + q * 160] = w[(size_t)i * 1280 + t + q * 160];
    }
    __syncthreads();
    #pragma unroll
    for (int d = 0; d < 8; d++) {
        g_wt[(size_t)(i * 8 + d) * JO + t] =
            __float2half(sh[(t >> 4) * 128 + (t & 15) * 8 + d]);
    }
    if (t < 10) {
        g_c[i * 10 + t] = 0.1f;
        g_blog[i * 10 + t] = 0.f;
    }
}

// GEMM s: part[split][b][jo] = sum_k xh[b][k] * (c[i(k),j(jo)] * Wt[k][jo]).
// 256 threads (8 warps), tile 64 b x 160 jo, 18 k-steps of 16.
// warp: wr = w&3 -> row tile, wc = w>>2 -> 80-col half (10 n-tiles).
__global__ __launch_bounds__(256) void k_gemm_s() {
    __shared__ __align__(16) __half As[64 * 24];
    __shared__ __align__(16) __half Bs[16 * 168];
    const int t = threadIdx.x;
    const int lane = t & 31;
    const int w = t >> 5;
    const int wr = w & 3;
    const int wc = w >> 2;
    const int split = blockIdx.x;
    const int m0 = blockIdx.y * 64;
    const int kbase = split * KCHUNK;

    float acc[10][4];
    #pragma unroll
    for (int n = 0; n < 10; n++) {
        #pragma unroll
        for (int q = 0; q < 4; q++) acc[n][q] = 0.f;
    }

    const unsigned int aaddr = smem_u32(As) +
        (unsigned int)(((wr * 16 + (lane & 15)) * 24 + (lane >> 4) * 8) * 2);
    const unsigned int baddr = smem_u32(Bs) +
        (unsigned int)(((lane & 15) * 168) * 2);

    for (int kk = 0; kk < 18; kk++) {
        const int k0 = kbase + kk * 16;
        #pragma unroll
        for (int q = 0; q < 2; q++) {          // A: 64x16 halves = 512 u32
            int idx = t + q * 256;
            int r = idx >> 3;
            int c = (idx & 7) * 2;
            *(uint32_t*)(As + r * 24 + c) =
                *(const uint32_t*)(g_xh + (size_t)(m0 + r) * KD + k0 + c);
        }
        #pragma unroll
        for (int q = 0; q < 3; q++) {          // B: 16x160 halves = 640 uint2
            int e = t + q * 256;
            if (e < 640) {
                int r = e / 40;
                int c8 = e - r * 40;
                int k = k0 + r;
                int i = k >> 3;
                int j = c8 >> 2;
                float cw = g_c[i * 10 + j];
                uint2 raw = *(const uint2*)(g_wt + (size_t)k * JO + c8 * 4);
                __half2 h0 = *(__half2*)&raw.x;
                __half2 h1 = *(__half2*)&raw.y;
                float2 f0 = __half22float2(h0);
                float2 f1 = __half22float2(h1);
                __half2 o0 = __floats2half2_rn(cw * f0.x, cw * f0.y);
                __half2 o1 = __floats2half2_rn(cw * f1.x, cw * f1.y);
                uint2 outv;
                outv.x = *(unsigned int*)&o0;
                outv.y = *(unsigned int*)&o1;
                *(uint2*)(Bs + r * 168 + c8 * 4) = outv;
            }
        }
        __syncthreads();
        unsigned int a0, a1, a2, a3;
        ldsm_x4(a0, a1, a2, a3, aaddr);
        #pragma unroll
        for (int nt = 0; nt < 10; nt++) {
            unsigned int b0, b1;
            ldsm_x2t(b0, b1, baddr + (unsigned int)((wc * 80 + nt * 8) * 2));
            mma16816(acc[nt], a0, a1, a2, a3, b0, b1);
        }
        __syncthreads();
    }
    const int g = lane >> 2;
    const int c2 = (lane & 3) * 2;
    float* base = g_part + ((size_t)split * BB + m0) * JO;
    #pragma unroll
    for (int nt = 0; nt < 10; nt++) {
        int col = wc * 80 + nt * 8 + c2;
        int row = wr * 16 + g;
        *(float2*)(base + (size_t)row * JO + col) =
            make_float2(acc[nt][0], acc[nt][1]);
        *(float2*)(base + (size_t)(row + 8) * JO + col) =
            make_float2(acc[nt][2], acc[nt][3]);
    }
}

// squash: s = sum over 32 splits of part; v = squash(s).
// grid (BB, 2): block handles one b and one 80-wide jo half; 640 threads,
// 8 groups of 80, each group sums 4 splits.
__global__ __launch_bounds__(640) void k_squash(float* __restrict__ outp) {
    __shared__ float red[640];
    const int b = blockIdx.x;
    const int half = blockIdx.y;
    const int t = threadIdx.x;
    const int jl = t % 80;
    const int qq = t / 80;                 // 0..7
    const int jo = half * 80 + jl;
    float s = 0.f;
    #pragma unroll
    for (int sp = 0; sp < 4; sp++) {
        s += g_part[((size_t)(qq * 4 + sp) * BB + b) * JO + jo];
    }
    red[t] = s;
    __syncthreads();
    if (t < 80) {
        float sv = red[t];
        #pragma unroll
        for (int k = 1; k < 8; k++) sv += red[t + 80 * k];
        red[t] = sv;
    }
    __syncthreads();
    if (t < 80) {
        int base = (t >> 4) << 4;          // 16-aligned group within the 80
        float sq = 0.f;
        #pragma unroll
        for (int o = 0; o < 16; o++) {
            float z = red[base + o];
            sq += z * z;
        }
        float fac = (sq / (1.f + sq)) * rsqrtf(sq + 1e-9f);
        float v = red[t] * fac;
        g_vh[b * JO + jo] = __float2half(v);
        if (outp) outp[b * JO + jo] = v;
    }
}

// GEMM M + route fused: M[r][jo] = sum_b xt[r][b] * vh[b][jo]; then
// a[i][j] = sum_{d,o} Wt[r][jo] * M[r][jo] for the 8 capsules in this block;
// blog += a/256; c = softmax_j(blog). 128 threads, 64 rows per block.
__global__ __launch_bounds__(128) void k_gemm_mr() {
    __shared__ __align__(16) __half As[64 * 24];
    __shared__ __align__(16) __half Bs[16 * 168];
    __shared__ float sa[80];               // [cap 0..7][j 0..9]
    const int t = threadIdx.x;
    const int lane = t & 31;
    const int w = t >> 5;
    const int m0 = blockIdx.x * 64;
    const int i0 = m0 >> 3;

    float acc[20][4];
    #pragma unroll
    for (int n = 0; n < 20; n++) {
        #pragma unroll
        for (int q = 0; q < 4; q++) acc[n][q] = 0.f;
    }

    const unsigned int aaddr = smem_u32(As) +
        (unsigned int)(((w * 16 + (lane & 15)) * 24 + (lane >> 4) * 8) * 2);
    const unsigned int baddr = smem_u32(Bs) +
        (unsigned int)(((lane & 15) * 168) * 2);

    for (int kk = 0; kk < 16; kk++) {
        const int k0 = kk * 16;
        #pragma unroll
        for (int q = 0; q < 4; q++) {          // A: 64x16 halves = 512 u32
            int idx = t + q * 128;
            int r = idx >> 3;
            int c = (idx & 7) * 2;
            *(uint32_t*)(As + r * 24 + c) =
                *(const uint32_t*)(g_xt + (size_t)(m0 + r) * BB + k0 + c);
        }
        #pragma unroll
        for (int q = 0; q < 5; q++) {          // B: 16x160 halves = 640 uint2
            int e = t + q * 128;
            int r = e / 40;
            int c8 = e - r * 40;
            *(uint2*)(Bs + r * 168 + c8 * 4) =
                *(const uint2*)(g_vh + (size_t)(k0 + r) * JO + c8 * 4);
        }
        __syncthreads();
        unsigned int a0, a1, a2, a3;
        ldsm_x4(a0, a1, a2, a3, aaddr);
        #pragma unroll
        for (int nt = 0; nt < 20; nt++) {
            unsigned int b0, b1;
            ldsm_x2t(b0, b1, baddr + (unsigned int)((nt * 8) * 2));
            mma16816(acc[nt], a0, a1, a2, a3, b0, b1);
        }
        __syncthreads();
    }

    // route epilogue: lane holds rows r1 = m0+w*16+g (cap w*2) and r1+8
    // (cap w*2+1), cols nt*8+c2, +1. Dot with Wt, reduce across warp.
    const int g = lane >> 2;
    const int c2 = (lane & 3) * 2;
    const int r1 = m0 + w * 16 + g;
    const int r2 = r1 + 8;
    float p0[10];
    float p1[10];
    #pragma unroll
    for (int j = 0; j < 10; j++) { p0[j] = 0.f; p1[j] = 0.f; }
    #pragma unroll
    for (int nt = 0; nt < 20; nt++) {
        int col = nt * 8 + c2;
        int j = nt >> 1;
        __half2 w1 = *(const __half2*)(g_wt + (size_t)r1 * JO + col);
        __half2 w2 = *(const __half2*)(g_wt + (size_t)r2 * JO + col);
        float2 f1 = __half22float2(w1);
        float2 f2 = __half22float2(w2);
        p0[j] += acc[nt][0] * f1.x + acc[nt][1] * f1.y;
        p1[j] += acc[nt][2] * f2.x + acc[nt][3] * f2.y;
    }
    #pragma unroll
    for (int j = 0; j < 10; j++) {
        #pragma unroll
        for (int off = 16; off > 0; off >>= 1) {
            p0[j] += __shfl_xor_sync(0xffffffffu, p0[j], off);
            p1[j] += __shfl_xor_sync(0xffffffffu, p1[j], off);
        }
    }
    if (lane == 0) {
        #pragma unroll
        for (int j = 0; j < 10; j++) {
            sa[(w * 2) * 10 + j] = p0[j];
            sa[(w * 2 + 1) * 10 + j] = p1[j];
        }
    }
    __syncthreads();
    if (t < 8) {
        const int i = i0 + t;
        float bl[10];
        float ex[10];
        float mx = -1e30f;
        #pragma unroll
        for (int j = 0; j < 10; j++) {
            float nb = g_blog[i * 10 + j] + sa[t * 10 + j] * (1.0f / 256.0f);
            g_blog[i * 10 + j] = nb;
            bl[j] = nb;
            mx = fmaxf(mx, nb);
        }
        float sum = 0.f;
        #pragma unroll
        for (int j = 0; j < 10; j++) {
            ex[j] = expf(bl[j] - mx);
            sum += ex[j];
        }
        float inv = 1.f / sum;
        #pragma unroll
        for (int j = 0; j < 10; j++) {
            g_c[i * 10 + j] = ex[j] * inv;
        }
    }
}

extern "C" void kernel_launch(void* const* d_in, const int* in_sizes, int n_in,
                              void* d_out, int out_size) {
    const float* x = (const float*)d_in[0];
    const float* w = (const float*)d_in[1];
    if (n_in >= 2 && in_sizes[0] == NIN * NOUT * DOUT * DIN
                  && in_sizes[1] == BB * DIN * NIN) {
        const float* tmp = x;
        x = w;
        w = tmp;
    }
    float* out = (float*)d_out;

    k_prep_x<<<dim3(KD / 32, BB / 32), 256>>>(x);
    k_prep_w<<<NIN, 160>>>(w);

    k_gemm_s<<<dim3(KSPLIT, 4), 256>>>();
    k_squash<<<dim3(BB, 2), 640>>>((float*)0);
    k_gemm_mr<<<KD / 64, 128>>>();

    k_gemm_s<<<dim3(KSPLIT, 4), 256>>>();
    k_squash<<<dim3(BB, 2), 640>>>((float*)0);
    k_gemm_mr<<<KD / 64, 128>>>();

    k_gemm_s<<<dim3(KSPLIT, 4), 256>>>();
    k_squash<<<dim3(BB, 2), 640>>>(out);
}

// round 6
// speedup vs baseline: 2.8739x; 1.0553x over previous
#include <cuda_runtime.h>
#include <cuda_fp16.h>
#include <cstdint>
#include <cstddef>

// problem constants
#define NIN   1152
#define NOUT  10
#define DIN   8
#define DOUT  16
#define BB    256
#define JO    160
#define KD    9216
#define IJ    11520
#define KSPLIT 32
#define KCHUNK 288

// Row index convention for the contraction dim: r = i*8 + d  (capsule-major).
// scratch (static device globals, no runtime allocation)
__device__ __half g_xh[(size_t)BB * KD];      // [b][r]
__device__ __half g_xt[(size_t)KD * BB];      // [r][b]
__device__ __half g_wt[(size_t)KD * JO];      // [r][jo]  unscaled W
__device__ __half g_wc[(size_t)KD * JO];      // [r][jo]  c-scaled W (per iter)
__device__ __half g_vh[BB * JO];              // [b][jo]
__device__ float  g_s[BB * JO];               // s accumulator (RED target)
__device__ float  g_blog[IJ];

__device__ __forceinline__ unsigned int smem_u32(const void* p) {
    return (unsigned int)__cvta_generic_to_shared(p);
}

__device__ __forceinline__ void ldsm_x4(unsigned int& r0, unsigned int& r1,
                                        unsigned int& r2, unsigned int& r3,
                                        unsigned int addr) {
    asm volatile("ldmatrix.sync.aligned.m8n8.x4.shared.b16 {%0,%1,%2,%3}, [%4];"
                 : "=r"(r0), "=r"(r1), "=r"(r2), "=r"(r3) : "r"(addr));
}

__device__ __forceinline__ void ldsm_x2t(unsigned int& r0, unsigned int& r1,
                                         unsigned int addr) {
    asm volatile("ldmatrix.sync.aligned.m8n8.x2.trans.shared.b16 {%0,%1}, [%2];"
                 : "=r"(r0), "=r"(r1) : "r"(addr));
}

__device__ __forceinline__ void mma16816(float* c,
                                         unsigned int a0, unsigned int a1,
                                         unsigned int a2, unsigned int a3,
                                         unsigned int b0, unsigned int b1) {
    asm volatile(
        "mma.sync.aligned.m16n8k16.row.col.f32.f16.f16.f32 "
        "{%0,%1,%2,%3}, {%4,%5,%6,%7}, {%8,%9}, {%0,%1,%2,%3};"
        : "+f"(c[0]), "+f"(c[1]), "+f"(c[2]), "+f"(c[3])
        : "r"(a0), "r"(a1), "r"(a2), "r"(a3), "r"(b0), "r"(b1));
}

// prep_x: xh[b][i*8+d] = fp16(x[b][d*NIN+i]); xt transposed likewise.
// 32x32 tiles; each tile lies within a single d (NIN divisible by 32).
__global__ __launch_bounds__(256) void k_prep_x(const float* __restrict__ x) {
    __shared__ float tile[32][33];
    const int di0 = blockIdx.x * 32;
    const int b0  = blockIdx.y * 32;
    const int d     = di0 / NIN;
    const int ibase = di0 - d * NIN;
    const int tx = threadIdx.x & 31;
    const int ty = threadIdx.x >> 5;
    #pragma unroll
    for (int q = 0; q < 4; q++) {
        int r = ty + q * 8;
        float v = x[(size_t)(b0 + r) * KD + di0 + tx];
        tile[r][tx] = v;
        g_xh[(size_t)(b0 + r) * KD + (ibase + tx) * 8 + d] = __float2half(v);
    }
    __syncthreads();
    #pragma unroll
    for (int q = 0; q < 4; q++) {
        int r = ty + q * 8;
        g_xt[(size_t)((ibase + r) * 8 + d) * BB + b0 + tx] = __float2half(tile[tx][r]);
    }
}

// prep_w: Wt[(i*8+d)][jo] = fp16(W[i][j][o][d]); Wc = 0.1*W (iter-1 coupling);
// init blog = 0; zero g_s.
__global__ __launch_bounds__(160) void k_prep_w(const float* __restrict__ w) {
    __shared__ float sh[1280];
    const int i = blockIdx.x;
    const int t = threadIdx.x;
    #pragma unroll
    for (int q = 0; q < 8; q++) {
        sh[t + q * 160] = w[(size_t)i * 1280 + t + q * 160];
    }
    __syncthreads();
    #pragma unroll
    for (int d = 0; d < 8; d++) {
        float raw = sh[(t >> 4) * 128 + (t & 15) * 8 + d];
        g_wt[(size_t)(i * 8 + d) * JO + t] = __float2half(raw);
        g_wc[(size_t)(i * 8 + d) * JO + t] = __float2half(0.1f * raw);
    }
    if (t < 10) {
        g_blog[i * 10 + t] = 0.f;
    }
    int gid = i * 160 + t;
    if (gid < BB * JO) g_s[gid] = 0.f;
}

// GEMM s: g_s[b][jo] += sum_k xh[b][k] * Wc[k][jo] over this split's K-chunk.
// 256 threads (8 warps), tile 64 b x 160 jo, 18 k-steps of 16.
// B stage is a pure copy (Wc prescaled). Epilogue: RED into g_s.
__global__ __launch_bounds__(256) void k_gemm_s() {
    __shared__ __align__(16) __half As[64 * 24];
    __shared__ __align__(16) __half Bs[16 * 168];
    const int t = threadIdx.x;
    const int lane = t & 31;
    const int w = t >> 5;
    const int wr = w & 3;
    const int wc = w >> 2;
    const int split = blockIdx.x;
    const int m0 = blockIdx.y * 64;
    const int kbase = split * KCHUNK;

    float acc[10][4];
    #pragma unroll
    for (int n = 0; n < 10; n++) {
        #pragma unroll
        for (int q = 0; q < 4; q++) acc[n][q] = 0.f;
    }

    const unsigned int aaddr = smem_u32(As) +
        (unsigned int)(((wr * 16 + (lane & 15)) * 24 + (lane >> 4) * 8) * 2);
    const unsigned int baddr = smem_u32(Bs) +
        (unsigned int)(((lane & 15) * 168) * 2);

    for (int kk = 0; kk < 18; kk++) {
        const int k0 = kbase + kk * 16;
        #pragma unroll
        for (int q = 0; q < 2; q++) {          // A: 64x16 halves = 512 u32
            int idx = t + q * 256;
            int r = idx >> 3;
            int c = (idx & 7) * 2;
            *(uint32_t*)(As + r * 24 + c) =
                *(const uint32_t*)(g_xh + (size_t)(m0 + r) * KD + k0 + c);
        }
        #pragma unroll
        for (int q = 0; q < 3; q++) {          // B: 16x160 halves = 640 uint2
            int e = t + q * 256;
            if (e < 640) {
                int r = e / 40;
                int c8 = e - r * 40;
                *(uint2*)(Bs + r * 168 + c8 * 4) =
                    *(const uint2*)(g_wc + (size_t)(k0 + r) * JO + c8 * 4);
            }
        }
        __syncthreads();
        unsigned int a0, a1, a2, a3;
        ldsm_x4(a0, a1, a2, a3, aaddr);
        #pragma unroll
        for (int nt = 0; nt < 10; nt++) {
            unsigned int b0, b1;
            ldsm_x2t(b0, b1, baddr + (unsigned int)((wc * 80 + nt * 8) * 2));
            mma16816(acc[nt], a0, a1, a2, a3, b0, b1);
        }
        __syncthreads();
    }
    const int g = lane >> 2;
    const int c2 = (lane & 3) * 2;
    float* base = g_s + (size_t)m0 * JO;
    #pragma unroll
    for (int nt = 0; nt < 10; nt++) {
        int col = wc * 80 + nt * 8 + c2;
        int row = wr * 16 + g;
        atomicAdd(base + (size_t)row * JO + col,       acc[nt][0]);
        atomicAdd(base + (size_t)row * JO + col + 1,   acc[nt][1]);
        atomicAdd(base + (size_t)(row + 8) * JO + col,     acc[nt][2]);
        atomicAdd(base + (size_t)(row + 8) * JO + col + 1, acc[nt][3]);
    }
}

// squash: v = squash(g_s); store fp16 v (+ fp32 out on last iter);
// zero g_s for the next iteration's accumulation.
__global__ __launch_bounds__(160) void k_squash(float* __restrict__ outp) {
    __shared__ float sh[JO];
    const int b = blockIdx.x;
    const int t = threadIdx.x;
    float s = g_s[b * JO + t];
    sh[t] = s * s;
    __syncthreads();
    const int base = (t >> 4) << 4;
    float sq = 0.f;
    #pragma unroll
    for (int o = 0; o < 16; o++) sq += sh[base + o];
    float fac = (sq / (1.f + sq)) * rsqrtf(sq + 1e-9f);
    float v = s * fac;
    g_vh[b * JO + t] = __float2half(v);
    if (outp) outp[b * JO + t] = v;
    g_s[b * JO + t] = 0.f;
}

// GEMM M + route fused: M[r][jo] = sum_b xt[r][b] * vh[b][jo]; then
// a[i][j] = sum_{d,o} Wt[r][jo] * M[r][jo] for the 8 capsules in this block;
// blog += a/256; c = softmax_j(blog) kept in smem; write Wc = c*Wt for the
// next iteration. 128 threads, 64 rows per block.
__global__ __launch_bounds__(128) void k_gemm_mr() {
    __shared__ __align__(16) __half As[64 * 24];
    __shared__ __align__(16) __half Bs[16 * 168];
    __shared__ float sa[80];               // agreement [cap 0..7][j 0..9]
    __shared__ float sc[80];               // softmax   [cap 0..7][j 0..9]
    const int t = threadIdx.x;
    const int lane = t & 31;
    const int w = t >> 5;
    const int m0 = blockIdx.x * 64;
    const int i0 = m0 >> 3;

    float acc[20][4];
    #pragma unroll
    for (int n = 0; n < 20; n++) {
        #pragma unroll
        for (int q = 0; q < 4; q++) acc[n][q] = 0.f;
    }

    const unsigned int aaddr = smem_u32(As) +
        (unsigned int)(((w * 16 + (lane & 15)) * 24 + (lane >> 4) * 8) * 2);
    const unsigned int baddr = smem_u32(Bs) +
        (unsigned int)(((lane & 15) * 168) * 2);

    for (int kk = 0; kk < 16; kk++) {
        const int k0 = kk * 16;
        #pragma unroll
        for (int q = 0; q < 4; q++) {          // A: 64x16 halves = 512 u32
            int idx = t + q * 128;
            int r = idx >> 3;
            int c = (idx & 7) * 2;
            *(uint32_t*)(As + r * 24 + c) =
                *(const uint32_t*)(g_xt + (size_t)(m0 + r) * BB + k0 + c);
        }
        #pragma unroll
        for (int q = 0; q < 5; q++) {          // B: 16x160 halves = 640 uint2
            int e = t + q * 128;
            int r = e / 40;
            int c8 = e - r * 40;
            *(uint2*)(Bs + r * 168 + c8 * 4) =
                *(const uint2*)(g_vh + (size_t)(k0 + r) * JO + c8 * 4);
        }
        __syncthreads();
        unsigned int a0, a1, a2, a3;
        ldsm_x4(a0, a1, a2, a3, aaddr);
        #pragma unroll
        for (int nt = 0; nt < 20; nt++) {
            unsigned int b0, b1;
            ldsm_x2t(b0, b1, baddr + (unsigned int)((nt * 8) * 2));
            mma16816(acc[nt], a0, a1, a2, a3, b0, b1);
        }
        __syncthreads();
    }

    // route epilogue: lane holds rows r1 = m0+w*16+g (cap w*2) and r1+8
    // (cap w*2+1), cols nt*8+c2, +1. Dot with Wt, reduce across warp.
    const int g = lane >> 2;
    const int c2 = (lane & 3) * 2;
    const int r1 = m0 + w * 16 + g;
    const int r2 = r1 + 8;
    float p0[10];
    float p1[10];
    #pragma unroll
    for (int j = 0; j < 10; j++) { p0[j] = 0.f; p1[j] = 0.f; }
    #pragma unroll
    for (int nt = 0; nt < 20; nt++) {
        int col = nt * 8 + c2;
        int j = nt >> 1;
        __half2 w1 = *(const __half2*)(g_wt + (size_t)r1 * JO + col);
        __half2 w2 = *(const __half2*)(g_wt + (size_t)r2 * JO + col);
        float2 f1 = __half22float2(w1);
        float2 f2 = __half22float2(w2);
        p0[j] += acc[nt][0] * f1.x + acc[nt][1] * f1.y;
        p1[j] += acc[nt][2] * f2.x + acc[nt][3] * f2.y;
    }
    #pragma unroll
    for (int j = 0; j < 10; j++) {
        #pragma unroll
        for (int off = 16; off > 0; off >>= 1) {
            p0[j] += __shfl_xor_sync(0xffffffffu, p0[j], off);
            p1[j] += __shfl_xor_sync(0xffffffffu, p1[j], off);
        }
    }
    if (lane == 0) {
        #pragma unroll
        for (int j = 0; j < 10; j++) {
            sa[(w * 2) * 10 + j] = p0[j];
            sa[(w * 2 + 1) * 10 + j] = p1[j];
        }
    }
    __syncthreads();
    if (t < 8) {
        const int i = i0 + t;
        float bl[10];
        float ex[10];
        float mx = -1e30f;
        #pragma unroll
        for (int j = 0; j < 10; j++) {
            float nb = g_blog[i * 10 + j] + sa[t * 10 + j] * (1.0f / 256.0f);
            g_blog[i * 10 + j] = nb;
            bl[j] = nb;
            mx = fmaxf(mx, nb);
        }
        float sum = 0.f;
        #pragma unroll
        for (int j = 0; j < 10; j++) {
            ex[j] = expf(bl[j] - mx);
            sum += ex[j];
        }
        float inv = 1.f / sum;
        #pragma unroll
        for (int j = 0; j < 10; j++) {
            sc[t * 10 + j] = ex[j] * inv;
        }
    }
    __syncthreads();

    // write Wc = c * Wt for this block's 64 rows (next iteration's B).
    #pragma unroll
    for (int q = 0; q < 20; q++) {             // 64 rows x 40 uint2 = 2560
        int e = t + q * 128;
        int r = e / 40;
        int c8 = e - r * 40;
        int j = c8 >> 2;
        float cw = sc[(r >> 3) * 10 + j];
        uint2 raw = *(const uint2*)(g_wt + (size_t)(m0 + r) * JO + c8 * 4);
        __half2 h0 = *(__half2*)&raw.x;
        __half2 h1 = *(__half2*)&raw.y;
        float2 f0 = __half22float2(h0);
        float2 f1 = __half22float2(h1);
        __half2 o0 = __floats2half2_rn(cw * f0.x, cw * f0.y);
        __half2 o1 = __floats2half2_rn(cw * f1.x, cw * f1.y);
        uint2 outv;
        outv.x = *(unsigned int*)&o0;
        outv.y = *(unsigned int*)&o1;
        *(uint2*)(g_wc + (size_t)(m0 + r) * JO + c8 * 4) = outv;
    }
}

extern "C" void kernel_launch(void* const* d_in, const int* in_sizes, int n_in,
                              void* d_out, int out_size) {
    const float* x = (const float*)d_in[0];
    const float* w = (const float*)d_in[1];
    if (n_in >= 2 && in_sizes[0] == NIN * NOUT * DOUT * DIN
                  && in_sizes[1] == BB * DIN * NIN) {
        const float* tmp = x;
        x = w;
        w = tmp;
    }
    float* out = (float*)d_out;

    k_prep_x<<<dim3(KD / 32, BB / 32), 256>>>(x);
    k_prep_w<<<NIN, 160>>>(w);

    k_gemm_s<<<dim3(KSPLIT, 4), 256>>>();
    k_squash<<<BB, 160>>>((float*)0);
    k_gemm_mr<<<KD / 64, 128>>>();

    k_gemm_s<<<dim3(KSPLIT, 4), 256>>>();
    k_squash<<<BB, 160>>>((float*)0);
    k_gemm_mr<<<KD / 64, 128>>>();

    k_gemm_s<<<dim3(KSPLIT, 4), 256>>>();
    k_squash<<<BB, 160>>>(out);
}